// round 10
// baseline (speedup 1.0000x reference)
#include <cuda_runtime.h>
#include <cuda_bf16.h>
#include <math.h>
#include <stdint.h>

#define SEQ 3136
#define NB 4
#define MTOK (NB*SEQ)   // 12544
#define PLN 50176       // 224*224

typedef unsigned long long u64;
typedef unsigned int u32;

// ---------------- f32x2 helpers (conv kernels) ----------------
__device__ __forceinline__ u64 pk2(float v) {
    u64 r; unsigned int u = __float_as_uint(v);
    asm("mov.b64 %0, {%1, %1};" : "=l"(r) : "r"(u));
    return r;
}
__device__ __forceinline__ void ffma2(u64& d, u64 a, u64 b) {
    asm("fma.rn.f32x2 %0, %1, %2, %0;" : "+l"(d) : "l"(a), "l"(b));
}
__device__ __forceinline__ float2 up2(u64 v) {
    unsigned int lo, hi;
    asm("mov.b64 {%0, %1}, %2;" : "=r"(lo), "=r"(hi) : "l"(v));
    return make_float2(__uint_as_float(lo), __uint_as_float(hi));
}

// ---------------- tf32 mma helpers ----------------
__device__ __forceinline__ float f2tf(float f) {
    u32 r; asm("cvt.rna.tf32.f32 %0, %1;" : "=r"(r) : "f"(f));
    return __uint_as_float(r);
}
__device__ __forceinline__ void mma_tf32(float* d, const u32* a, const u32* b) {
    asm("mma.sync.aligned.m16n8k8.row.col.f32.tf32.tf32.f32 "
        "{%0,%1,%2,%3},{%4,%5,%6,%7},{%8,%9},{%0,%1,%2,%3};"
        : "+f"(d[0]), "+f"(d[1]), "+f"(d[2]), "+f"(d[3])
        : "r"(a[0]), "r"(a[1]), "r"(a[2]), "r"(a[3]), "r"(b[0]), "r"(b[1]));
}
__device__ __forceinline__ u32 su(const float* p) { return __float_as_uint(*p); }

// ---------------- cp.async helpers ----------------
__device__ __forceinline__ void cpa16(float* dst_smem, const float* src) {
    u32 d = (u32)__cvta_generic_to_shared(dst_smem);
    asm volatile("cp.async.cg.shared.global [%0], [%1], 16;" :: "r"(d), "l"(src));
}
__device__ __forceinline__ void cp_commit() { asm volatile("cp.async.commit_group;"); }
__device__ __forceinline__ void cp_wait0()  { asm volatile("cp.async.wait_group 0;"); }

// ---------------- device scratch (256B-aligned) ----------------
__device__ __align__(256) unsigned long long g_b1[NB*9*PLN];
__device__ __align__(256) unsigned int       g_b2[NB*3*PLN];
__device__ __align__(256) float              g_h3[NB*3*PLN];
__device__ __align__(256) float              g_w1s[9*3136];
__device__ __align__(256) ulonglong2         g_w2m[3*49*32];
__device__ __align__(256) uint2              g_w3m[3*3*49];
__device__ __align__(256) float              g_tok[(size_t)NB*256*112*112];
__device__ __align__(256) float              g_z[MTOK*256];
__device__ __align__(256) float              g_hbuf[MTOK*256];
__device__ __align__(256) float              g_qkv[MTOK*768];
__device__ __align__(256) float              g_obuf[MTOK*256];
__device__ __align__(256) float              g_mlp[MTOK*512];
__device__ __align__(256) float              g_logits[MTOK];
__device__ __align__(256) float              g_pooled[NB*256];
// pre-rounded tf32 weights
__device__ __align__(256) float              g_qkvwt[7*768*256];
__device__ __align__(256) float              g_projwt[7*256*256];
__device__ __align__(256) float              g_fc1wt[7*512*256];
__device__ __align__(256) float              g_fc2wt[7*256*512];

// ---------------- pack weights (BNN masks) ----------------
__global__ void pack_kernel(const float* __restrict__ w1, const float* __restrict__ w2,
                            const float* __restrict__ w3) {
    int tid = blockIdx.x * blockDim.x + threadIdx.x;
    if (tid < 9*3136) {
        int plane = tid / 3136, idx = tid % 3136;
        int t = idx >> 6, co = idx & 63;
        int ci = plane / 3, dz = plane % 3;
        float w = w1[((co*3 + ci)*3 + dz)*49 + t];
        g_w1s[tid] = (w > 0.f) ? 1.f : ((w < 0.f) ? -1.f : 0.f);
    }
    if (tid < 32*3*49) {
        int co = tid / 147, rem = tid % 147;
        int dz = rem / 49, t = rem % 49;
        unsigned long long pos = 0ull, neg = 0ull;
        for (int ci = 0; ci < 64; ci++) {
            float w = w2[((co*64 + ci)*3 + dz)*49 + t];
            if (w > 0.f) pos |= 1ull << ci; else if (w < 0.f) neg |= 1ull << ci;
        }
        g_w2m[(dz*49 + t)*32 + co] = make_ulonglong2(pos, neg);
    }
    if (tid < 3*3*49) {
        int co = tid / 147, rem = tid % 147;
        int dz = rem / 49, t = rem % 49;
        unsigned int pos = 0u, neg = 0u;
        for (int ci = 0; ci < 32; ci++) {
            float w = w3[((co*32 + ci)*3 + dz)*49 + t];
            if (w > 0.f) pos |= 1u << ci; else if (w < 0.f) neg |= 1u << ci;
        }
        g_w3m[tid] = make_uint2(pos, neg);
    }
}

// ---------------- pre-round encoder weights to tf32 ----------------
__global__ void packw_kernel(const float* __restrict__ qkvw, const float* __restrict__ projw,
                             const float* __restrict__ fc1w, const float* __restrict__ fc2w) {
    int i = blockIdx.x * 256 + threadIdx.x;
    if (i < 7*768*256) g_qkvwt[i] = f2tf(qkvw[i]);
    if (i < 7*256*256) g_projwt[i] = f2tf(projw[i]);
    if (i < 7*512*256) g_fc1wt[i] = f2tf(fc1w[i]);
    if (i < 7*256*512) g_fc2wt[i] = f2tf(fc2w[i]);
}

// ---------------- conv1: fp32 (f32x2), pack sign bits ----------------
__global__ void __launch_bounds__(256) conv1_kernel(const float* __restrict__ x) {
    int bd = blockIdx.y;
    int b = bd / 9, d = bd % 9;
    int ty0 = (blockIdx.x / 14) * 16, tx0 = (blockIdx.x % 14) * 16;
    int tid = threadIdx.x;
    int ly = tid >> 4, lx = tid & 15;

    __shared__ __align__(16) float pl[22*22];
    __shared__ __align__(16) float ws[49][64];

    u64 acc2[32];
#pragma unroll
    for (int i = 0; i < 32; i++) acc2[i] = 0ull;

    for (int ci = 0; ci < 3; ci++) {
        for (int dz = 0; dz < 3; dz++) {
            int din = 3*d - 1 + dz;
            bool dv = (din >= 0 && din < 27);
            for (int idx = tid; idx < 3136; idx += 256)
                ((float*)ws)[idx] = g_w1s[(ci*3 + dz)*3136 + idx];
            const float* xp = x + ((size_t)((b*3 + ci)*27 + (dv ? din : 0)))*PLN;
            for (int idx = tid; idx < 484; idx += 256) {
                int yy = ty0 - 3 + idx / 22, xx = tx0 - 3 + idx % 22;
                float v = 0.f;
                if (dv && yy >= 0 && yy < 224 && xx >= 0 && xx < 224) v = xp[yy*224 + xx];
                pl[idx] = v;
            }
            __syncthreads();
#pragma unroll 7
            for (int t = 0; t < 49; t++) {
                float v = pl[(ly + t/7)*22 + lx + (t%7)];
                u64 vv = pk2(v);
                const ulonglong2* wp = (const ulonglong2*)&ws[t][0];
#pragma unroll
                for (int c = 0; c < 16; c++) {
                    ulonglong2 w2 = wp[c];
                    ffma2(acc2[2*c+0], vv, w2.x);
                    ffma2(acc2[2*c+1], vv, w2.y);
                }
            }
            __syncthreads();
        }
    }
    unsigned long long bits = 0ull;
#pragma unroll
    for (int c = 0; c < 32; c++) {
        float2 f = up2(acc2[c]);
        if (f.x > 0.f) bits |= (1ull << (2*c));
        if (f.y > 0.f) bits |= (1ull << (2*c+1));
    }
    g_b1[((size_t)bd*224 + ty0 + ly)*224 + tx0 + lx] = bits;
}

// ---------------- conv2: 64-bit popcount conv ----------------
__global__ void __launch_bounds__(256) conv2_kernel() {
    int bd = blockIdx.y;
    int b = bd / 3, d = bd % 3;
    int ty0 = (blockIdx.x / 14) * 16, tx0 = (blockIdx.x % 14) * 16;
    int tid = threadIdx.x;
    int ly = tid >> 4, lx = tid & 15;

    __shared__ __align__(16) unsigned long long pl[22*22];
    __shared__ __align__(16) ulonglong2 mk[49*32];

    int acc[32];
#pragma unroll
    for (int i = 0; i < 32; i++) acc[i] = 0;

    for (int dz = 0; dz < 3; dz++) {
        int din = 3*d - 1 + dz;
        bool dv = (din >= 0 && din < 9);
        const unsigned long long* ip = g_b1 + (size_t)(b*9 + (dv ? din : 0))*PLN;
        for (int idx = tid; idx < 484; idx += 256) {
            int yy = ty0 - 3 + idx / 22, xx = tx0 - 3 + idx % 22;
            unsigned long long v = 0ull;
            if (dv && yy >= 0 && yy < 224 && xx >= 0 && xx < 224) v = ip[yy*224 + xx];
            pl[idx] = v;
        }
        for (int idx = tid; idx < 1568; idx += 256) mk[idx] = g_w2m[dz*1568 + idx];
        __syncthreads();
        for (int t = 0; t < 49; t++) {
            unsigned long long v = pl[(ly + t/7)*22 + lx + (t%7)];
            if (v) {
#pragma unroll
                for (int co = 0; co < 32; co++) {
                    ulonglong2 m = mk[t*32 + co];
                    acc[co] += __popcll(v & m.x) - __popcll(v & m.y);
                }
            }
        }
        __syncthreads();
    }
    unsigned int bits = 0u;
#pragma unroll
    for (int i = 0; i < 32; i++) if (acc[i] > 0) bits |= (1u << i);
    g_b2[((size_t)bd*224 + ty0 + ly)*224 + tx0 + lx] = bits;
}

// ---------------- conv3: 32-bit popcount conv -> relu float ----------------
__global__ void conv3_kernel() {
    int idx = blockIdx.x * 256 + threadIdx.x;
    if (idx >= NB*PLN) return;
    int b = idx / PLN, p = idx % PLN;
    int y = p / 224, x = p % 224;
    int a0 = 0, a1 = 0, a2 = 0;
    for (int dz = 1; dz < 3; dz++) {
        const unsigned int* ip = g_b2 + (size_t)(b*3 + dz - 1)*PLN;
        for (int ky = 0; ky < 7; ky++) {
            int yy = y - 3 + ky; if ((unsigned)yy >= 224u) continue;
            for (int kx = 0; kx < 7; kx++) {
                int xx = x - 3 + kx; if ((unsigned)xx >= 224u) continue;
                unsigned int v = ip[yy*224 + xx];
                if (!v) continue;
                int t = ky*7 + kx;
                uint2 m0 = g_w3m[(0*3 + dz)*49 + t];
                uint2 m1 = g_w3m[(1*3 + dz)*49 + t];
                uint2 m2 = g_w3m[(2*3 + dz)*49 + t];
                a0 += __popc(v & m0.x) - __popc(v & m0.y);
                a1 += __popc(v & m1.x) - __popc(v & m1.y);
                a2 += __popc(v & m2.x) - __popc(v & m2.y);
            }
        }
    }
    g_h3[(size_t)(b*3 + 0)*PLN + p] = a0 > 0 ? (float)a0 : 0.f;
    g_h3[(size_t)(b*3 + 1)*PLN + p] = a1 > 0 ? (float)a1 : 0.f;
    g_h3[(size_t)(b*3 + 2)*PLN + p] = a2 > 0 ? (float)a2 : 0.f;
}

// ---------------- tokenizer conv: 3->256, k7 s2 p3, relu (f32x2) ----------------
__global__ void __launch_bounds__(256) tok_kernel(const float* __restrict__ tokw) {
    int tile = blockIdx.x;
    int cg = blockIdx.y;
    int b = blockIdx.z;
    int ty0 = (tile / 7) * 16, tx0 = (tile % 7) * 16;
    int tid = threadIdx.x;
    int ly = tid >> 4, lx = tid & 15;

    __shared__ __align__(16) float pls[3*37*37 + 1];
    __shared__ __align__(16) float ws[49][32];

    for (int idx = tid; idx < 3*1369; idx += 256) {
        int ci = idx / 1369, r = idx % 1369;
        int iy = 2*ty0 - 3 + r / 37, ix = 2*tx0 - 3 + r % 37;
        float v = 0.f;
        if (iy >= 0 && iy < 224 && ix >= 0 && ix < 224)
            v = g_h3[(size_t)(b*3 + ci)*PLN + iy*224 + ix];
        pls[idx] = v;
    }

    u64 acc2[16];
#pragma unroll
    for (int i = 0; i < 16; i++) acc2[i] = 0ull;

    for (int ci = 0; ci < 3; ci++) {
        __syncthreads();
        for (int idx = tid; idx < 1568; idx += 256) {
            int t = idx >> 5, c = idx & 31;
            ws[t][c] = tokw[((cg*32 + c)*3 + ci)*49 + t];
        }
        __syncthreads();
#pragma unroll 7
        for (int t = 0; t < 49; t++) {
            float v = pls[ci*1369 + (2*ly + t/7)*37 + 2*lx + (t%7)];
            u64 vv = pk2(v);
            const ulonglong2* wp = (const ulonglong2*)&ws[t][0];
#pragma unroll
            for (int c = 0; c < 8; c++) {
                ulonglong2 w2 = wp[c];
                ffma2(acc2[2*c+0], vv, w2.x);
                ffma2(acc2[2*c+1], vv, w2.y);
            }
        }
    }
    int oy = ty0 + ly, ox = tx0 + lx;
#pragma unroll
    for (int c = 0; c < 16; c++) {
        float2 f = up2(acc2[c]);
        g_tok[(((size_t)b*256 + cg*32 + 2*c+0)*112 + oy)*112 + ox] = f.x > 0.f ? f.x : 0.f;
        g_tok[(((size_t)b*256 + cg*32 + 2*c+1)*112 + oy)*112 + ox] = f.y > 0.f ? f.y : 0.f;
    }
}

// ---------------- maxpool 3x3 s2 p1 + transpose + pos_emb ----------------
__global__ void pool_kernel(const float* __restrict__ pos) {
    int bc = blockIdx.x;
    int b = bc >> 8, c = bc & 255;
    const float* tp = g_tok + (size_t)bc*12544;
    for (int n = threadIdx.x; n < SEQ; n += 256) {
        int oy = n / 56, ox = n % 56;
        float mx = -1e30f;
        for (int ky = 0; ky < 3; ky++) {
            int iy = 2*oy - 1 + ky; if ((unsigned)iy >= 112u) continue;
            for (int kx = 0; kx < 3; kx++) {
                int ix = 2*ox - 1 + kx; if ((unsigned)ix >= 112u) continue;
                mx = fmaxf(mx, tp[iy*112 + ix]);
            }
        }
        g_z[((size_t)b*SEQ + n)*256 + c] = mx + pos[n*256 + c];
    }
}

// ---------------- LayerNorm (warp per row); rnd -> tf32-round output ----------------
__global__ void ln_kernel(const float* __restrict__ X, const float* __restrict__ gam,
                          const float* __restrict__ bet, float* __restrict__ Y, int rnd,
                          const float* __restrict__ poolw, const float* __restrict__ poolb,
                          float* __restrict__ logits) {
    int row = blockIdx.x*8 + (threadIdx.x >> 5);
    int lane = threadIdx.x & 31;
    const float* xr = X + (size_t)row*256;
    float4 a = *(const float4*)(xr + lane*4);
    float4 b4 = *(const float4*)(xr + 128 + lane*4);
    float s = a.x+a.y+a.z+a.w + b4.x+b4.y+b4.z+b4.w;
#pragma unroll
    for (int o = 16; o; o >>= 1) s += __shfl_xor_sync(0xffffffffu, s, o);
    float mean = s * (1.f/256.f);
    float d0=a.x-mean, d1=a.y-mean, d2=a.z-mean, d3=a.w-mean;
    float e0=b4.x-mean, e1=b4.y-mean, e2=b4.z-mean, e3=b4.w-mean;
    float vs = d0*d0+d1*d1+d2*d2+d3*d3 + e0*e0+e1*e1+e2*e2+e3*e3;
#pragma unroll
    for (int o = 16; o; o >>= 1) vs += __shfl_xor_sync(0xffffffffu, vs, o);
    float rinv = rsqrtf(vs * (1.f/256.f) + 1e-5f);
    int c0 = lane*4, c1 = 128 + lane*4;
    float4 g0 = *(const float4*)(gam + c0), g1 = *(const float4*)(gam + c1);
    float4 t0 = *(const float4*)(bet + c0), t1 = *(const float4*)(bet + c1);
    float4 y0 = make_float4(d0*rinv*g0.x+t0.x, d1*rinv*g0.y+t0.y, d2*rinv*g0.z+t0.z, d3*rinv*g0.w+t0.w);
    float4 y1 = make_float4(e0*rinv*g1.x+t1.x, e1*rinv*g1.y+t1.y, e2*rinv*g1.z+t1.z, e3*rinv*g1.w+t1.w);
    if (rnd) {
        y0.x = f2tf(y0.x); y0.y = f2tf(y0.y); y0.z = f2tf(y0.z); y0.w = f2tf(y0.w);
        y1.x = f2tf(y1.x); y1.y = f2tf(y1.y); y1.z = f2tf(y1.z); y1.w = f2tf(y1.w);
    }
    float* yr = Y + (size_t)row*256;
    *(float4*)(yr + c0) = y0;
    *(float4*)(yr + c1) = y1;
    if (logits) {
        float4 p0 = *(const float4*)(poolw + c0), p1 = *(const float4*)(poolw + c1);
        float dt = y0.x*p0.x+y0.y*p0.y+y0.z*p0.z+y0.w*p0.w
                 + y1.x*p1.x+y1.y*p1.y+y1.z*p1.z+y1.w*p1.w;
#pragma unroll
        for (int o = 16; o; o >>= 1) dt += __shfl_xor_sync(0xffffffffu, dt, o);
        if (lane == 0) logits[row] = dt + poolb[0];
    }
}

// ---------------- cp.async stage for GEMM ----------------
__device__ __forceinline__ void gemm_issue(float* As, float* Bs, const float* A, const float* B,
                                           int m0, int n0, int K, int k0, int tid) {
#pragma unroll
    for (int i = 0; i < 4; i++) {
        int c = tid + 128*i, row = c >> 2, q = c & 3;
        cpa16(As + row*20 + q*4, A + (size_t)(m0+row)*K + k0 + q*4);
    }
#pragma unroll
    for (int i = 0; i < 2; i++) {
        int c = tid + 128*i, row = c >> 2, q = c & 3;
        cpa16(Bs + row*20 + q*4, B + (size_t)(n0+row)*K + k0 + q*4);
    }
    cp_commit();
}

// ---------------- tf32 tensor-core NT GEMM, cp.async double-buffered ----------------
// All operands pre-rounded tf32. epi: 0 = bias+round, 1 = bias+gelu+round, 2 = bias+residual (fp32 out)
__global__ void __launch_bounds__(128) gemm_tc(const float* __restrict__ A, const float* __restrict__ B,
                                               const float* __restrict__ bias, const float* __restrict__ res,
                                               float* __restrict__ C, int M, int N, int K, int epi) {
    __shared__ __align__(16) float As[2][128*20];
    __shared__ __align__(16) float Bs[2][64*20];
    int m0 = blockIdx.y*128, n0 = blockIdx.x*64;
    int tid = threadIdx.x;
    int w = tid >> 5, lane = tid & 31;
    int g = lane >> 2, t4 = lane & 3;

    float c[2][8][4];
#pragma unroll
    for (int mt = 0; mt < 2; mt++)
#pragma unroll
        for (int nt = 0; nt < 8; nt++)
#pragma unroll
            for (int i = 0; i < 4; i++) c[mt][nt][i] = 0.f;

    gemm_issue(As[0], Bs[0], A, B, m0, n0, K, 0, tid);
    int KT = K >> 4;
    int buf = 0;
    for (int it = 0; it < KT; it++) {
        cp_wait0();
        __syncthreads();
        if (it + 1 < KT)
            gemm_issue(As[buf^1], Bs[buf^1], A, B, m0, n0, K, (it+1)*16, tid);
        const float* Ab = As[buf];
        const float* Bb = Bs[buf];
#pragma unroll
        for (int kk = 0; kk < 2; kk++) {
            int kb = kk*8;
            u32 a[2][4];
#pragma unroll
            for (int mt = 0; mt < 2; mt++) {
                int r = w*32 + mt*16 + g;
                a[mt][0] = su(&Ab[r*20 + kb + t4]);
                a[mt][1] = su(&Ab[(r+8)*20 + kb + t4]);
                a[mt][2] = su(&Ab[r*20 + kb + t4 + 4]);
                a[mt][3] = su(&Ab[(r+8)*20 + kb + t4 + 4]);
            }
#pragma unroll
            for (int nt = 0; nt < 8; nt++) {
                u32 b[2];
                b[0] = su(&Bb[(nt*8 + g)*20 + kb + t4]);
                b[1] = su(&Bb[(nt*8 + g)*20 + kb + t4 + 4]);
                mma_tf32(c[0][nt], a[0], b);
                mma_tf32(c[1][nt], a[1], b);
            }
        }
        buf ^= 1;
    }
    // epilogue
#pragma unroll
    for (int mt = 0; mt < 2; mt++) {
        int r = m0 + w*32 + mt*16 + g;
#pragma unroll
        for (int nt = 0; nt < 8; nt++) {
            int col = n0 + nt*8 + 2*t4;
            float2 bb = *(const float2*)(bias + col);
            float v0 = c[mt][nt][0] + bb.x, v1 = c[mt][nt][1] + bb.y;
            float v2 = c[mt][nt][2] + bb.x, v3 = c[mt][nt][3] + bb.y;
            if (epi == 1) {
                v0 = v0*0.5f*(1.f + erff(v0*0.70710678118654752f));
                v1 = v1*0.5f*(1.f + erff(v1*0.70710678118654752f));
                v2 = v2*0.5f*(1.f + erff(v2*0.70710678118654752f));
                v3 = v3*0.5f*(1.f + erff(v3*0.70710678118654752f));
            } else if (epi == 2) {
                float2 r0 = *(const float2*)&res[(size_t)r*N + col];
                float2 r1 = *(const float2*)&res[(size_t)(r+8)*N + col];
                v0 += r0.x; v1 += r0.y; v2 += r1.x; v3 += r1.y;
            }
            if (epi != 2) {   // output feeds another tf32 matmul -> pre-round
                v0 = f2tf(v0); v1 = f2tf(v1); v2 = f2tf(v2); v3 = f2tf(v3);
            }
            *(float2*)&C[(size_t)r*N + col] = make_float2(v0, v1);
            *(float2*)&C[(size_t)(r+8)*N + col] = make_float2(v2, v3);
        }
    }
}

// ---------------- cp.async stage for attention K/V tile ----------------
__device__ __forceinline__ void attn_issueKV(float* Ks, float* Vs, const float* base,
                                             int kt, int h, int tid) {
#pragma unroll
    for (int i = 0; i < 8; i++) {
        int c = tid + 128*i, row = c >> 4, q = c & 15;
        cpa16(Ks + row*68 + q*4, base + (size_t)(kt*64 + row)*768 + 256 + h*64 + q*4);
    }
#pragma unroll
    for (int i = 0; i < 8; i++) {
        int c = tid + 128*i, row = c >> 4, q = c & 15;
        cpa16(Vs + row*72 + q*4, base + (size_t)(kt*64 + row)*768 + 512 + h*64 + q*4);
    }
    cp_commit();
}

// ---------------- tf32 flash attention, cp.async double-buffered K/V ----------------
// smem floats: Q 64*68 | P 64*68 | K 2*64*68 | V 2*64*72  = 26624 floats
#define ATTN_SMEM (26624*4)
__global__ void __launch_bounds__(128) attn_tc(const float* __restrict__ qkv, float* __restrict__ out) {
    extern __shared__ __align__(16) float sm[];
    float* Qs  = sm;                 // [q][d] pitch 68 (pre-scaled by 1/8)
    float* Ps  = sm + 4352;          // [q][key] pitch 68
    float* Kb0 = sm + 8704;          // [key][d] pitch 68
    float* Kb1 = sm + 13056;
    float* Vb0 = sm + 17408;         // [key][d] pitch 72
    float* Vb1 = sm + 22016;
    int qt = blockIdx.x, h = blockIdx.y, b = blockIdx.z;
    int tid = threadIdx.x;
    int w = tid >> 5, lane = tid & 31;
    int g = lane >> 2, t4 = lane & 3;
    int qb = w*16;
    const float* base = qkv + (size_t)b*SEQ*768;

    { // load Q (values already tf32-rounded; *0.125 is exact)
        int row = tid >> 1, half = (tid & 1)*32;
        const float* qp = base + (size_t)(qt*64 + row)*768 + h*64 + half;
#pragma unroll
        for (int i = 0; i < 8; i++) {
            float4 v = *(const float4*)(qp + i*4);
            v.x *= 0.125f; v.y *= 0.125f; v.z *= 0.125f; v.w *= 0.125f;
            *(float4*)&Qs[row*68 + half + i*4] = v;
        }
    }
    attn_issueKV(Kb0, Vb0, base, 0, h, tid);

    float o[8][4];
#pragma unroll
    for (int nt = 0; nt < 8; nt++)
#pragma unroll
        for (int i = 0; i < 4; i++) o[nt][i] = 0.f;
    float m0r = -1e30f, m1r = -1e30f, l0 = 0.f, l1 = 0.f;

    for (int kt = 0; kt < 49; kt++) {
        float* Ks = (kt & 1) ? Kb1 : Kb0;
        float* Vs = (kt & 1) ? Vb1 : Vb0;
        cp_wait0();
        __syncthreads();
        if (kt + 1 < 49)
            attn_issueKV((kt & 1) ? Kb0 : Kb1, (kt & 1) ? Vb0 : Vb1, base, kt+1, h, tid);

        // S = Q K^T   (warp: m16 x n64)
        float s[8][4];
#pragma unroll
        for (int nt = 0; nt < 8; nt++)
#pragma unroll
            for (int i = 0; i < 4; i++) s[nt][i] = 0.f;
#pragma unroll
        for (int kk = 0; kk < 8; kk++) {
            int kb = kk*8;
            u32 a[4];
            a[0] = su(&Qs[(qb+g)*68 + kb + t4]);
            a[1] = su(&Qs[(qb+g+8)*68 + kb + t4]);
            a[2] = su(&Qs[(qb+g)*68 + kb + t4 + 4]);
            a[3] = su(&Qs[(qb+g+8)*68 + kb + t4 + 4]);
#pragma unroll
            for (int nt = 0; nt < 8; nt++) {
                u32 bfr[2];
                bfr[0] = su(&Ks[(nt*8+g)*68 + kb + t4]);
                bfr[1] = su(&Ks[(nt*8+g)*68 + kb + t4 + 4]);
                mma_tf32(s[nt], a, bfr);
            }
        }

        // online softmax (rows g, g+8 of this warp's q-tile)
        float mx0 = -1e30f, mx1 = -1e30f;
#pragma unroll
        for (int nt = 0; nt < 8; nt++) {
            mx0 = fmaxf(mx0, fmaxf(s[nt][0], s[nt][1]));
            mx1 = fmaxf(mx1, fmaxf(s[nt][2], s[nt][3]));
        }
        mx0 = fmaxf(mx0, __shfl_xor_sync(0xffffffffu, mx0, 1));
        mx0 = fmaxf(mx0, __shfl_xor_sync(0xffffffffu, mx0, 2));
        mx1 = fmaxf(mx1, __shfl_xor_sync(0xffffffffu, mx1, 1));
        mx1 = fmaxf(mx1, __shfl_xor_sync(0xffffffffu, mx1, 2));
        float mn0 = fmaxf(m0r, mx0), mn1 = fmaxf(m1r, mx1);
        float sc0 = __expf(m0r - mn0), sc1 = __expf(m1r - mn1);
        m0r = mn0; m1r = mn1;
        l0 *= sc0; l1 *= sc1;
#pragma unroll
        for (int nt = 0; nt < 8; nt++) {
            o[nt][0] *= sc0; o[nt][1] *= sc0;
            o[nt][2] *= sc1; o[nt][3] *= sc1;
        }
        float rs0 = 0.f, rs1 = 0.f;
#pragma unroll
        for (int nt = 0; nt < 8; nt++) {
            float p0 = __expf(s[nt][0] - mn0);
            float p1 = __expf(s[nt][1] - mn0);
            float p2 = __expf(s[nt][2] - mn1);
            float p3 = __expf(s[nt][3] - mn1);
            rs0 += p0 + p1; rs1 += p2 + p3;
            *(float2*)&Ps[(qb+g)*68 + nt*8 + 2*t4]   = make_float2(f2tf(p0), f2tf(p1));
            *(float2*)&Ps[(qb+g+8)*68 + nt*8 + 2*t4] = make_float2(f2tf(p2), f2tf(p3));
        }
        rs0 += __shfl_xor_sync(0xffffffffu, rs0, 1);
        rs0 += __shfl_xor_sync(0xffffffffu, rs0, 2);
        rs1 += __shfl_xor_sync(0xffffffffu, rs1, 1);
        rs1 += __shfl_xor_sync(0xffffffffu, rs1, 2);
        l0 += rs0; l1 += rs1;
        __syncwarp();

        // O += P V  (A = P row-major q x key; B = V^T col-major -> read V[key][d])
#pragma unroll
        for (int kk = 0; kk < 8; kk++) {
            int kb = kk*8;
            u32 a[4];
            a[0] = su(&Ps[(qb+g)*68 + kb + t4]);
            a[1] = su(&Ps[(qb+g+8)*68 + kb + t4]);
            a[2] = su(&Ps[(qb+g)*68 + kb + t4 + 4]);
            a[3] = su(&Ps[(qb+g+8)*68 + kb + t4 + 4]);
#pragma unroll
            for (int nt = 0; nt < 8; nt++) {
                u32 bfr[2];
                bfr[0] = su(&Vs[(kb+t4)*72 + nt*8 + g]);
                bfr[1] = su(&Vs[(kb+t4+4)*72 + nt*8 + g]);
                mma_tf32(o[nt], a, bfr);
            }
        }
    }
    float inv0 = 1.f / l0, inv1 = 1.f / l1;
    int r0 = b*SEQ + qt*64 + qb + g;
#pragma unroll
    for (int nt = 0; nt < 8; nt++) {
        int col = h*64 + nt*8 + 2*t4;
        // round: obuf feeds proj GEMM as tf32 A-operand
        *(float2*)&out[(size_t)r0*256 + col]     = make_float2(f2tf(o[nt][0]*inv0), f2tf(o[nt][1]*inv0));
        *(float2*)&out[(size_t)(r0+8)*256 + col] = make_float2(f2tf(o[nt][2]*inv1), f2tf(o[nt][3]*inv1));
    }
}

// ---------------- sequence pooling softmax ----------------
__global__ void softpool_kernel() {
    __shared__ __align__(16) float e[SEQ];
    __shared__ __align__(16) float red[256];
    int b = blockIdx.x, tid = threadIdx.x;
    const float* lg = g_logits + b*SEQ;
    float mx = -1e30f;
    for (int n = tid; n < SEQ; n += 256) mx = fmaxf(mx, lg[n]);
    red[tid] = mx; __syncthreads();
    for (int s = 128; s; s >>= 1) { if (tid < s) red[tid] = fmaxf(red[tid], red[tid+s]); __syncthreads(); }
    mx = red[0]; __syncthreads();
    float sum = 0.f;
    for (int n = tid; n < SEQ; n += 256) { float ee = __expf(lg[n] - mx); e[n] = ee; sum += ee; }
    red[tid] = sum; __syncthreads();
    for (int s = 128; s; s >>= 1) { if (tid < s) red[tid] += red[tid+s]; __syncthreads(); }
    float inv = 1.f / red[0];
    const float* zb = g_hbuf + (size_t)b*SEQ*256;
    float acc = 0.f;
    for (int n = 0; n < SEQ; n++) acc = fmaf(e[n], zb[(size_t)n*256 + tid], acc);
    g_pooled[b*256 + tid] = acc * inv;
}

// ---------------- classifier head ----------------
__global__ void head_kernel(const float* __restrict__ hw, const float* __restrict__ hb,
                            float* __restrict__ out) {
    int t = threadIdx.x + blockIdx.x*blockDim.x;
    if (t >= NB*101) return;
    int b = t / 101, c = t % 101;
    const float* p = g_pooled + b*256;
    const float* w = hw + c*256;
    float acc = 0.f;
    for (int k = 0; k < 256; k++) acc = fmaf(p[k], w[k], acc);
    out[t] = acc + hb[c];
}

// ---------------- launcher ----------------
extern "C" void kernel_launch(void* const* d_in, const int* in_sizes, int n_in,
                              void* d_out, int out_size) {
    const float* x      = (const float*)d_in[0];
    const float* w1     = (const float*)d_in[1];
    const float* w2     = (const float*)d_in[2];
    const float* w3     = (const float*)d_in[3];
    const float* tokw   = (const float*)d_in[4];
    const float* pos    = (const float*)d_in[5];
    const float* ln1s   = (const float*)d_in[6];
    const float* ln1b   = (const float*)d_in[7];
    const float* qkvw   = (const float*)d_in[8];
    const float* qkvb   = (const float*)d_in[9];
    const float* projw  = (const float*)d_in[10];
    const float* projb  = (const float*)d_in[11];
    const float* ln2s   = (const float*)d_in[12];
    const float* ln2b   = (const float*)d_in[13];
    const float* fc1w   = (const float*)d_in[14];
    const float* fc1b   = (const float*)d_in[15];
    const float* fc2w   = (const float*)d_in[16];
    const float* fc2b   = (const float*)d_in[17];
    const float* lnfs   = (const float*)d_in[18];
    const float* lnfb   = (const float*)d_in[19];
    const float* poolw  = (const float*)d_in[20];
    const float* poolb  = (const float*)d_in[21];
    const float* headw  = (const float*)d_in[22];
    const float* headb  = (const float*)d_in[23];
    float* out = (float*)d_out;

    cudaFuncSetAttribute(attn_tc, cudaFuncAttributeMaxDynamicSharedMemorySize, ATTN_SMEM);

    float *zb, *hb_, *qk, *ob, *ml, *lg;
    float *wqkv, *wproj, *wfc1, *wfc2;
    cudaGetSymbolAddress((void**)&zb, g_z);
    cudaGetSymbolAddress((void**)&hb_, g_hbuf);
    cudaGetSymbolAddress((void**)&qk, g_qkv);
    cudaGetSymbolAddress((void**)&ob, g_obuf);
    cudaGetSymbolAddress((void**)&ml, g_mlp);
    cudaGetSymbolAddress((void**)&lg, g_logits);
    cudaGetSymbolAddress((void**)&wqkv, g_qkvwt);
    cudaGetSymbolAddress((void**)&wproj, g_projwt);
    cudaGetSymbolAddress((void**)&wfc1, g_fc1wt);
    cudaGetSymbolAddress((void**)&wfc2, g_fc2wt);

    pack_kernel<<<(9*3136 + 255)/256, 256>>>(w1, w2, w3);
    packw_kernel<<<(7*768*256 + 255)/256, 256>>>(qkvw, projw, fc1w, fc2w);
    conv1_kernel<<<dim3(196, 36), 256>>>(x);
    conv2_kernel<<<dim3(196, 12), 256>>>();
    conv3_kernel<<<(NB*PLN + 255)/256, 256>>>();
    tok_kernel<<<dim3(49, 8, NB), 256>>>(tokw);
    pool_kernel<<<NB*256, 256>>>(pos);

    for (int lyr = 0; lyr < 7; lyr++) {
        ln_kernel<<<1568, 256>>>(zb, ln1s + lyr*256, ln1b + lyr*256, hb_, 1, 0, 0, 0);
        gemm_tc<<<dim3(12, 98), 128>>>(hb_, wqkv + (size_t)lyr*768*256, qkvb + lyr*768, 0, qk,
                                       MTOK, 768, 256, 0);
        attn_tc<<<dim3(49, 4, NB), 128, ATTN_SMEM>>>(qk, ob);
        gemm_tc<<<dim3(4, 98), 128>>>(ob, wproj + (size_t)lyr*256*256, projb + lyr*256, zb, zb,
                                      MTOK, 256, 256, 2);
        ln_kernel<<<1568, 256>>>(zb, ln2s + lyr*256, ln2b + lyr*256, hb_, 1, 0, 0, 0);
        gemm_tc<<<dim3(8, 98), 128>>>(hb_, wfc1 + (size_t)lyr*512*256, fc1b + lyr*512, 0, ml,
                                      MTOK, 512, 256, 1);
        gemm_tc<<<dim3(4, 98), 128>>>(ml, wfc2 + (size_t)lyr*256*512, fc2b + lyr*256, zb, zb,
                                      MTOK, 256, 512, 2);
    }

    ln_kernel<<<1568, 256>>>(zb, lnfs, lnfb, hb_, 0, poolw, poolb, lg);
    softpool_kernel<<<NB, 256>>>();
    head_kernel<<<2, 256>>>(headw, headb, out);
}

// round 15
// speedup vs baseline: 1.1243x; 1.1243x over previous
#include <cuda_runtime.h>
#include <cuda_bf16.h>
#include <math.h>
#include <stdint.h>

#define SEQ 3136
#define NB 4
#define MTOK (NB*SEQ)   // 12544
#define PLN 50176       // 224*224

typedef unsigned long long u64;
typedef unsigned int u32;

// ---------------- f32x2 helpers (conv kernels) ----------------
__device__ __forceinline__ u64 pk2(float v) {
    u64 r; unsigned int u = __float_as_uint(v);
    asm("mov.b64 %0, {%1, %1};" : "=l"(r) : "r"(u));
    return r;
}
__device__ __forceinline__ void ffma2(u64& d, u64 a, u64 b) {
    asm("fma.rn.f32x2 %0, %1, %2, %0;" : "+l"(d) : "l"(a), "l"(b));
}
__device__ __forceinline__ float2 up2(u64 v) {
    unsigned int lo, hi;
    asm("mov.b64 {%0, %1}, %2;" : "=r"(lo), "=r"(hi) : "l"(v));
    return make_float2(__uint_as_float(lo), __uint_as_float(hi));
}

// ---------------- tf32 mma helpers ----------------
__device__ __forceinline__ float f2tf(float f) {
    u32 r; asm("cvt.rna.tf32.f32 %0, %1;" : "=r"(r) : "f"(f));
    return __uint_as_float(r);
}
__device__ __forceinline__ void mma_tf32(float* d, const u32* a, const u32* b) {
    asm("mma.sync.aligned.m16n8k8.row.col.f32.tf32.tf32.f32 "
        "{%0,%1,%2,%3},{%4,%5,%6,%7},{%8,%9},{%0,%1,%2,%3};"
        : "+f"(d[0]), "+f"(d[1]), "+f"(d[2]), "+f"(d[3])
        : "r"(a[0]), "r"(a[1]), "r"(a[2]), "r"(a[3]), "r"(b[0]), "r"(b[1]));
}
__device__ __forceinline__ u32 su(const float* p) { return __float_as_uint(*p); }

// ---------------- cp.async helpers ----------------
__device__ __forceinline__ void cpa16(float* dst_smem, const float* src) {
    u32 d = (u32)__cvta_generic_to_shared(dst_smem);
    asm volatile("cp.async.cg.shared.global [%0], [%1], 16;" :: "r"(d), "l"(src));
}
__device__ __forceinline__ void cp_commit() { asm volatile("cp.async.commit_group;"); }
__device__ __forceinline__ void cp_wait0()  { asm volatile("cp.async.wait_group 0;"); }

// ---------------- device scratch (256B-aligned) ----------------
__device__ __align__(256) unsigned long long g_b1[NB*9*PLN];
__device__ __align__(256) unsigned int       g_b2[NB*3*PLN];
__device__ __align__(256) float              g_h3[NB*3*PLN];
__device__ __align__(256) float              g_w1s[9*3136];
__device__ __align__(256) ulonglong2         g_w2m[3*49*32];
__device__ __align__(256) uint2              g_w3m[3*3*49];
__device__ __align__(256) float              g_tok[(size_t)NB*256*112*112];
__device__ __align__(256) float              g_z[MTOK*256];
__device__ __align__(256) float              g_hbuf[MTOK*256];
__device__ __align__(256) float              g_qkv[MTOK*768];
__device__ __align__(256) float              g_obuf[MTOK*256];
__device__ __align__(256) float              g_mlp[MTOK*512];
__device__ __align__(256) float              g_logits[MTOK];
__device__ __align__(256) float              g_pooled[NB*256];
// pre-rounded tf32 weights
__device__ __align__(256) float              g_qkvwt[7*768*256];
__device__ __align__(256) float              g_projwt[7*256*256];
__device__ __align__(256) float              g_fc1wt[7*512*256];
__device__ __align__(256) float              g_fc2wt[7*256*512];

// ---------------- pack weights (BNN masks) ----------------
__global__ void pack_kernel(const float* __restrict__ w1, const float* __restrict__ w2,
                            const float* __restrict__ w3) {
    int tid = blockIdx.x * blockDim.x + threadIdx.x;
    if (tid < 9*3136) {
        int plane = tid / 3136, idx = tid % 3136;
        int t = idx >> 6, co = idx & 63;
        int ci = plane / 3, dz = plane % 3;
        float w = w1[((co*3 + ci)*3 + dz)*49 + t];
        g_w1s[tid] = (w > 0.f) ? 1.f : ((w < 0.f) ? -1.f : 0.f);
    }
    if (tid < 32*3*49) {
        int co = tid / 147, rem = tid % 147;
        int dz = rem / 49, t = rem % 49;
        unsigned long long pos = 0ull, neg = 0ull;
        for (int ci = 0; ci < 64; ci++) {
            float w = w2[((co*64 + ci)*3 + dz)*49 + t];
            if (w > 0.f) pos |= 1ull << ci; else if (w < 0.f) neg |= 1ull << ci;
        }
        g_w2m[(dz*49 + t)*32 + co] = make_ulonglong2(pos, neg);
    }
    if (tid < 3*3*49) {
        int co = tid / 147, rem = tid % 147;
        int dz = rem / 49, t = rem % 49;
        unsigned int pos = 0u, neg = 0u;
        for (int ci = 0; ci < 32; ci++) {
            float w = w3[((co*32 + ci)*3 + dz)*49 + t];
            if (w > 0.f) pos |= 1u << ci; else if (w < 0.f) neg |= 1u << ci;
        }
        g_w3m[tid] = make_uint2(pos, neg);
    }
}

// ---------------- pre-round encoder weights to tf32 ----------------
__global__ void packw_kernel(const float* __restrict__ qkvw, const float* __restrict__ projw,
                             const float* __restrict__ fc1w, const float* __restrict__ fc2w) {
    int i = blockIdx.x * 256 + threadIdx.x;
    if (i < 7*768*256) g_qkvwt[i] = f2tf(qkvw[i]);
    if (i < 7*256*256) g_projwt[i] = f2tf(projw[i]);
    if (i < 7*512*256) g_fc1wt[i] = f2tf(fc1w[i]);
    if (i < 7*256*512) g_fc2wt[i] = f2tf(fc2w[i]);
}

// ---------------- conv1: tensor-core (tf32 hi/lo split), pack sign bits ----------------
// Block 256 thr = 8 warps. Tile: 64 out-ch x 256 pixels (16x16).
// warp: wc = w>>1 -> channels [wc*16, wc*16+16); wp = w&1 -> pixels [wp*128, wp*128+128)
__global__ void __launch_bounds__(256) conv1_tc(const float* __restrict__ x) {
    int bd = blockIdx.y;
    int b = bd / 9, d = bd % 9;
    int ty0 = (blockIdx.x / 14) * 16, tx0 = (blockIdx.x % 14) * 16;
    int tid = threadIdx.x;
    int w = tid >> 5, lane = tid & 31;
    int wc = w >> 1, wp = w & 1;
    int g = lane >> 2, t4 = lane & 3;

    __shared__ __align__(16) float plh[506];       // halo tile hi (rows 0..22, row 22 zero)
    __shared__ __align__(16) float pll[506];       // halo tile lo
    __shared__ __align__(16) float ws[64*57];      // [ch][tap] pitch 57, taps 49..56 zero
    __shared__ unsigned short ob16[4*256];         // per-chgroup 16-bit output planes

    float c[16][4];
#pragma unroll
    for (int nt = 0; nt < 16; nt++)
#pragma unroll
        for (int i = 0; i < 4; i++) c[nt][i] = 0.f;

    for (int ci = 0; ci < 3; ci++) {
        for (int dz = 0; dz < 3; dz++) {
            int din = 3*d - 1 + dz;
            bool dv = (din >= 0 && din < 27);
            __syncthreads();   // previous chunk's mma reads done
            // weights: g_w1s layout [(ci*3+dz)*3136 + t*64 + co] -> ws[co*57+t]
            const float* wsrc = g_w1s + (ci*3 + dz)*3136;
            for (int idx = tid; idx < 3136; idx += 256) {
                int t = idx >> 6, co = idx & 63;
                ws[co*57 + t] = wsrc[idx];
            }
            for (int idx = tid; idx < 512; idx += 256) {
                int co = idx >> 3, t = 49 + (idx & 7);
                ws[co*57 + t] = 0.f;
            }
            // input halo tile: hi/lo split
            const float* xp = x + ((size_t)((b*3 + ci)*27 + (dv ? din : 0)))*PLN;
            for (int idx = tid; idx < 506; idx += 256) {
                float v = 0.f;
                if (idx < 484) {
                    int yy = ty0 - 3 + idx / 22, xx = tx0 - 3 + idx % 22;
                    if (dv && yy >= 0 && yy < 224 && xx >= 0 && xx < 224) v = xp[yy*224 + xx];
                }
                float h = f2tf(v);
                plh[idx] = h;
                pll[idx] = f2tf(v - h);
            }
            __syncthreads();
            // 7 k-chunks of 8 taps (taps 49..55 are zero-weight padding)
#pragma unroll
            for (int kc = 0; kc < 7; kc++) {
                int ta = kc*8 + t4, tb = ta + 4;
                int offa = (ta/7)*22 + ta%7;
                int offb = (tb/7)*22 + tb%7;
                u32 a[4];
                int chb = wc*16;
                a[0] = su(&ws[(chb + g)*57 + kc*8 + t4]);
                a[1] = su(&ws[(chb + g + 8)*57 + kc*8 + t4]);
                a[2] = su(&ws[(chb + g)*57 + kc*8 + t4 + 4]);
                a[3] = su(&ws[(chb + g + 8)*57 + kc*8 + t4 + 4]);
#pragma unroll
                for (int nt = 0; nt < 16; nt++) {
                    int pn = wp*128 + nt*8 + g;
                    int pix = (pn >> 4)*22 + (pn & 15);
                    u32 bh[2], bl[2];
                    bh[0] = su(&plh[pix + offa]);
                    bh[1] = su(&plh[pix + offb]);
                    mma_tf32(c[nt], a, bh);
                    bl[0] = su(&pll[pix + offa]);
                    bl[1] = su(&pll[pix + offb]);
                    mma_tf32(c[nt], a, bl);
                }
            }
        }
    }
    // binarize: bit(ch) = (acc > 0); reduce over g-lanes, store 16-bit plane
#pragma unroll
    for (int nt = 0; nt < 16; nt++) {
        u32 m0 = (c[nt][0] > 0.f ? (1u << g) : 0u) | (c[nt][2] > 0.f ? (1u << (g+8)) : 0u);
        u32 m1 = (c[nt][1] > 0.f ? (1u << g) : 0u) | (c[nt][3] > 0.f ? (1u << (g+8)) : 0u);
        m0 |= __shfl_xor_sync(0xffffffffu, m0, 4);
        m0 |= __shfl_xor_sync(0xffffffffu, m0, 8);
        m0 |= __shfl_xor_sync(0xffffffffu, m0, 16);
        m1 |= __shfl_xor_sync(0xffffffffu, m1, 4);
        m1 |= __shfl_xor_sync(0xffffffffu, m1, 8);
        m1 |= __shfl_xor_sync(0xffffffffu, m1, 16);
        if (g == 0) {
            int p0 = wp*128 + nt*8 + 2*t4;
            ob16[wc*256 + p0]     = (unsigned short)m0;
            ob16[wc*256 + p0 + 1] = (unsigned short)m1;
        }
    }
    __syncthreads();
    u64 bits = (u64)ob16[tid] | ((u64)ob16[256 + tid] << 16)
             | ((u64)ob16[512 + tid] << 32) | ((u64)ob16[768 + tid] << 48);
    g_b1[((size_t)bd*224 + ty0 + (tid >> 4))*224 + tx0 + (tid & 15)] = bits;
}

// ---------------- conv2: 64-bit popcount conv ----------------
__global__ void __launch_bounds__(256) conv2_kernel() {
    int bd = blockIdx.y;
    int b = bd / 3, d = bd % 3;
    int ty0 = (blockIdx.x / 14) * 16, tx0 = (blockIdx.x % 14) * 16;
    int tid = threadIdx.x;
    int ly = tid >> 4, lx = tid & 15;

    __shared__ __align__(16) unsigned long long pl[22*22];
    __shared__ __align__(16) ulonglong2 mk[49*32];

    int acc[32];
#pragma unroll
    for (int i = 0; i < 32; i++) acc[i] = 0;

    for (int dz = 0; dz < 3; dz++) {
        int din = 3*d - 1 + dz;
        bool dv = (din >= 0 && din < 9);
        const unsigned long long* ip = g_b1 + (size_t)(b*9 + (dv ? din : 0))*PLN;
        for (int idx = tid; idx < 484; idx += 256) {
            int yy = ty0 - 3 + idx / 22, xx = tx0 - 3 + idx % 22;
            unsigned long long v = 0ull;
            if (dv && yy >= 0 && yy < 224 && xx >= 0 && xx < 224) v = ip[yy*224 + xx];
            pl[idx] = v;
        }
        for (int idx = tid; idx < 1568; idx += 256) mk[idx] = g_w2m[dz*1568 + idx];
        __syncthreads();
        for (int t = 0; t < 49; t++) {
            unsigned long long v = pl[(ly + t/7)*22 + lx + (t%7)];
            if (v) {
#pragma unroll
                for (int co = 0; co < 32; co++) {
                    ulonglong2 m = mk[t*32 + co];
                    acc[co] += __popcll(v & m.x) - __popcll(v & m.y);
                }
            }
        }
        __syncthreads();
    }
    unsigned int bits = 0u;
#pragma unroll
    for (int i = 0; i < 32; i++) if (acc[i] > 0) bits |= (1u << i);
    g_b2[((size_t)bd*224 + ty0 + ly)*224 + tx0 + lx] = bits;
}

// ---------------- conv3: 32-bit popcount conv -> relu float ----------------
__global__ void conv3_kernel() {
    int idx = blockIdx.x * 256 + threadIdx.x;
    if (idx >= NB*PLN) return;
    int b = idx / PLN, p = idx % PLN;
    int y = p / 224, x = p % 224;
    int a0 = 0, a1 = 0, a2 = 0;
    for (int dz = 1; dz < 3; dz++) {
        const unsigned int* ip = g_b2 + (size_t)(b*3 + dz - 1)*PLN;
        for (int ky = 0; ky < 7; ky++) {
            int yy = y - 3 + ky; if ((unsigned)yy >= 224u) continue;
            for (int kx = 0; kx < 7; kx++) {
                int xx = x - 3 + kx; if ((unsigned)xx >= 224u) continue;
                unsigned int v = ip[yy*224 + xx];
                if (!v) continue;
                int t = ky*7 + kx;
                uint2 m0 = g_w3m[(0*3 + dz)*49 + t];
                uint2 m1 = g_w3m[(1*3 + dz)*49 + t];
                uint2 m2 = g_w3m[(2*3 + dz)*49 + t];
                a0 += __popc(v & m0.x) - __popc(v & m0.y);
                a1 += __popc(v & m1.x) - __popc(v & m1.y);
                a2 += __popc(v & m2.x) - __popc(v & m2.y);
            }
        }
    }
    g_h3[(size_t)(b*3 + 0)*PLN + p] = a0 > 0 ? (float)a0 : 0.f;
    g_h3[(size_t)(b*3 + 1)*PLN + p] = a1 > 0 ? (float)a1 : 0.f;
    g_h3[(size_t)(b*3 + 2)*PLN + p] = a2 > 0 ? (float)a2 : 0.f;
}

// ---------------- tokenizer conv: 3->256, k7 s2 p3, relu (f32x2) ----------------
__global__ void __launch_bounds__(256) tok_kernel(const float* __restrict__ tokw) {
    int tile = blockIdx.x;
    int cg = blockIdx.y;
    int b = blockIdx.z;
    int ty0 = (tile / 7) * 16, tx0 = (tile % 7) * 16;
    int tid = threadIdx.x;
    int ly = tid >> 4, lx = tid & 15;

    __shared__ __align__(16) float pls[3*37*37 + 1];
    __shared__ __align__(16) float ws[49][32];

    for (int idx = tid; idx < 3*1369; idx += 256) {
        int ci = idx / 1369, r = idx % 1369;
        int iy = 2*ty0 - 3 + r / 37, ix = 2*tx0 - 3 + r % 37;
        float v = 0.f;
        if (iy >= 0 && iy < 224 && ix >= 0 && ix < 224)
            v = g_h3[(size_t)(b*3 + ci)*PLN + iy*224 + ix];
        pls[idx] = v;
    }

    u64 acc2[16];
#pragma unroll
    for (int i = 0; i < 16; i++) acc2[i] = 0ull;

    for (int ci = 0; ci < 3; ci++) {
        __syncthreads();
        for (int idx = tid; idx < 1568; idx += 256) {
            int t = idx >> 5, c = idx & 31;
            ws[t][c] = tokw[((cg*32 + c)*3 + ci)*49 + t];
        }
        __syncthreads();
#pragma unroll 7
        for (int t = 0; t < 49; t++) {
            float v = pls[ci*1369 + (2*ly + t/7)*37 + 2*lx + (t%7)];
            u64 vv = pk2(v);
            const ulonglong2* wp = (const ulonglong2*)&ws[t][0];
#pragma unroll
            for (int c = 0; c < 8; c++) {
                ulonglong2 w2 = wp[c];
                ffma2(acc2[2*c+0], vv, w2.x);
                ffma2(acc2[2*c+1], vv, w2.y);
            }
        }
    }
    int oy = ty0 + ly, ox = tx0 + lx;
#pragma unroll
    for (int c = 0; c < 16; c++) {
        float2 f = up2(acc2[c]);
        g_tok[(((size_t)b*256 + cg*32 + 2*c+0)*112 + oy)*112 + ox] = f.x > 0.f ? f.x : 0.f;
        g_tok[(((size_t)b*256 + cg*32 + 2*c+1)*112 + oy)*112 + ox] = f.y > 0.f ? f.y : 0.f;
    }
}

// ---------------- maxpool 3x3 s2 p1 + transpose + pos_emb ----------------
__global__ void pool_kernel(const float* __restrict__ pos) {
    int bc = blockIdx.x;
    int b = bc >> 8, c = bc & 255;
    const float* tp = g_tok + (size_t)bc*12544;
    for (int n = threadIdx.x; n < SEQ; n += 256) {
        int oy = n / 56, ox = n % 56;
        float mx = -1e30f;
        for (int ky = 0; ky < 3; ky++) {
            int iy = 2*oy - 1 + ky; if ((unsigned)iy >= 112u) continue;
            for (int kx = 0; kx < 3; kx++) {
                int ix = 2*ox - 1 + kx; if ((unsigned)ix >= 112u) continue;
                mx = fmaxf(mx, tp[iy*112 + ix]);
            }
        }
        g_z[((size_t)b*SEQ + n)*256 + c] = mx + pos[n*256 + c];
    }
}

// ---------------- LayerNorm (warp per row); rnd -> tf32-round output ----------------
__global__ void ln_kernel(const float* __restrict__ X, const float* __restrict__ gam,
                          const float* __restrict__ bet, float* __restrict__ Y, int rnd,
                          const float* __restrict__ poolw, const float* __restrict__ poolb,
                          float* __restrict__ logits) {
    int row = blockIdx.x*8 + (threadIdx.x >> 5);
    int lane = threadIdx.x & 31;
    const float* xr = X + (size_t)row*256;
    float4 a = *(const float4*)(xr + lane*4);
    float4 b4 = *(const float4*)(xr + 128 + lane*4);
    float s = a.x+a.y+a.z+a.w + b4.x+b4.y+b4.z+b4.w;
#pragma unroll
    for (int o = 16; o; o >>= 1) s += __shfl_xor_sync(0xffffffffu, s, o);
    float mean = s * (1.f/256.f);
    float d0=a.x-mean, d1=a.y-mean, d2=a.z-mean, d3=a.w-mean;
    float e0=b4.x-mean, e1=b4.y-mean, e2=b4.z-mean, e3=b4.w-mean;
    float vs = d0*d0+d1*d1+d2*d2+d3*d3 + e0*e0+e1*e1+e2*e2+e3*e3;
#pragma unroll
    for (int o = 16; o; o >>= 1) vs += __shfl_xor_sync(0xffffffffu, vs, o);
    float rinv = rsqrtf(vs * (1.f/256.f) + 1e-5f);
    int c0 = lane*4, c1 = 128 + lane*4;
    float4 g0 = *(const float4*)(gam + c0), g1 = *(const float4*)(gam + c1);
    float4 t0 = *(const float4*)(bet + c0), t1 = *(const float4*)(bet + c1);
    float4 y0 = make_float4(d0*rinv*g0.x+t0.x, d1*rinv*g0.y+t0.y, d2*rinv*g0.z+t0.z, d3*rinv*g0.w+t0.w);
    float4 y1 = make_float4(e0*rinv*g1.x+t1.x, e1*rinv*g1.y+t1.y, e2*rinv*g1.z+t1.z, e3*rinv*g1.w+t1.w);
    if (rnd) {
        y0.x = f2tf(y0.x); y0.y = f2tf(y0.y); y0.z = f2tf(y0.z); y0.w = f2tf(y0.w);
        y1.x = f2tf(y1.x); y1.y = f2tf(y1.y); y1.z = f2tf(y1.z); y1.w = f2tf(y1.w);
    }
    float* yr = Y + (size_t)row*256;
    *(float4*)(yr + c0) = y0;
    *(float4*)(yr + c1) = y1;
    if (logits) {
        float4 p0 = *(const float4*)(poolw + c0), p1 = *(const float4*)(poolw + c1);
        float dt = y0.x*p0.x+y0.y*p0.y+y0.z*p0.z+y0.w*p0.w
                 + y1.x*p1.x+y1.y*p1.y+y1.z*p1.z+y1.w*p1.w;
#pragma unroll
        for (int o = 16; o; o >>= 1) dt += __shfl_xor_sync(0xffffffffu, dt, o);
        if (lane == 0) logits[row] = dt + poolb[0];
    }
}

// ---------------- cp.async stage for GEMM ----------------
__device__ __forceinline__ void gemm_issue(float* As, float* Bs, const float* A, const float* B,
                                           int m0, int n0, int K, int k0, int tid) {
#pragma unroll
    for (int i = 0; i < 4; i++) {
        int c = tid + 128*i, row = c >> 2, q = c & 3;
        cpa16(As + row*20 + q*4, A + (size_t)(m0+row)*K + k0 + q*4);
    }
#pragma unroll
    for (int i = 0; i < 2; i++) {
        int c = tid + 128*i, row = c >> 2, q = c & 3;
        cpa16(Bs + row*20 + q*4, B + (size_t)(n0+row)*K + k0 + q*4);
    }
    cp_commit();
}

// ---------------- tf32 tensor-core NT GEMM, cp.async double-buffered ----------------
__global__ void __launch_bounds__(128) gemm_tc(const float* __restrict__ A, const float* __restrict__ B,
                                               const float* __restrict__ bias, const float* __restrict__ res,
                                               float* __restrict__ C, int M, int N, int K, int epi) {
    __shared__ __align__(16) float As[2][128*20];
    __shared__ __align__(16) float Bs[2][64*20];
    int m0 = blockIdx.y*128, n0 = blockIdx.x*64;
    int tid = threadIdx.x;
    int w = tid >> 5, lane = tid & 31;
    int g = lane >> 2, t4 = lane & 3;

    float c[2][8][4];
#pragma unroll
    for (int mt = 0; mt < 2; mt++)
#pragma unroll
        for (int nt = 0; nt < 8; nt++)
#pragma unroll
            for (int i = 0; i < 4; i++) c[mt][nt][i] = 0.f;

    gemm_issue(As[0], Bs[0], A, B, m0, n0, K, 0, tid);
    int KT = K >> 4;
    int buf = 0;
    for (int it = 0; it < KT; it++) {
        cp_wait0();
        __syncthreads();
        if (it + 1 < KT)
            gemm_issue(As[buf^1], Bs[buf^1], A, B, m0, n0, K, (it+1)*16, tid);
        const float* Ab = As[buf];
        const float* Bb = Bs[buf];
#pragma unroll
        for (int kk = 0; kk < 2; kk++) {
            int kb = kk*8;
            u32 a[2][4];
#pragma unroll
            for (int mt = 0; mt < 2; mt++) {
                int r = w*32 + mt*16 + g;
                a[mt][0] = su(&Ab[r*20 + kb + t4]);
                a[mt][1] = su(&Ab[(r+8)*20 + kb + t4]);
                a[mt][2] = su(&Ab[r*20 + kb + t4 + 4]);
                a[mt][3] = su(&Ab[(r+8)*20 + kb + t4 + 4]);
            }
#pragma unroll
            for (int nt = 0; nt < 8; nt++) {
                u32 b[2];
                b[0] = su(&Bb[(nt*8 + g)*20 + kb + t4]);
                b[1] = su(&Bb[(nt*8 + g)*20 + kb + t4 + 4]);
                mma_tf32(c[0][nt], a[0], b);
                mma_tf32(c[1][nt], a[1], b);
            }
        }
        buf ^= 1;
    }
    // epilogue
#pragma unroll
    for (int mt = 0; mt < 2; mt++) {
        int r = m0 + w*32 + mt*16 + g;
#pragma unroll
        for (int nt = 0; nt < 8; nt++) {
            int col = n0 + nt*8 + 2*t4;
            float2 bb = *(const float2*)(bias + col);
            float v0 = c[mt][nt][0] + bb.x, v1 = c[mt][nt][1] + bb.y;
            float v2 = c[mt][nt][2] + bb.x, v3 = c[mt][nt][3] + bb.y;
            if (epi == 1) {
                v0 = v0*0.5f*(1.f + erff(v0*0.70710678118654752f));
                v1 = v1*0.5f*(1.f + erff(v1*0.70710678118654752f));
                v2 = v2*0.5f*(1.f + erff(v2*0.70710678118654752f));
                v3 = v3*0.5f*(1.f + erff(v3*0.70710678118654752f));
            } else if (epi == 2) {
                float2 r0 = *(const float2*)&res[(size_t)r*N + col];
                float2 r1 = *(const float2*)&res[(size_t)(r+8)*N + col];
                v0 += r0.x; v1 += r0.y; v2 += r1.x; v3 += r1.y;
            }
            if (epi != 2) {
                v0 = f2tf(v0); v1 = f2tf(v1); v2 = f2tf(v2); v3 = f2tf(v3);
            }
            *(float2*)&C[(size_t)r*N + col] = make_float2(v0, v1);
            *(float2*)&C[(size_t)(r+8)*N + col] = make_float2(v2, v3);
        }
    }
}

// ---------------- cp.async stage for attention K/V tile ----------------
__device__ __forceinline__ void attn_issueKV(float* Ks, float* Vs, const float* base,
                                             int kt, int h, int tid) {
#pragma unroll
    for (int i = 0; i < 8; i++) {
        int c = tid + 128*i, row = c >> 4, q = c & 15;
        cpa16(Ks + row*68 + q*4, base + (size_t)(kt*64 + row)*768 + 256 + h*64 + q*4);
    }
#pragma unroll
    for (int i = 0; i < 8; i++) {
        int c = tid + 128*i, row = c >> 4, q = c & 15;
        cpa16(Vs + row*72 + q*4, base + (size_t)(kt*64 + row)*768 + 512 + h*64 + q*4);
    }
    cp_commit();
}

// ---------------- tf32 flash attention, cp.async double-buffered K/V ----------------
#define ATTN_SMEM (26624*4)
__global__ void __launch_bounds__(128) attn_tc(const float* __restrict__ qkv, float* __restrict__ out) {
    extern __shared__ __align__(16) float sm[];
    float* Qs  = sm;
    float* Ps  = sm + 4352;
    float* Kb0 = sm + 8704;
    float* Kb1 = sm + 13056;
    float* Vb0 = sm + 17408;
    float* Vb1 = sm + 22016;
    int qt = blockIdx.x, h = blockIdx.y, b = blockIdx.z;
    int tid = threadIdx.x;
    int w = tid >> 5, lane = tid & 31;
    int g = lane >> 2, t4 = lane & 3;
    int qb = w*16;
    const float* base = qkv + (size_t)b*SEQ*768;

    {
        int row = tid >> 1, half = (tid & 1)*32;
        const float* qp = base + (size_t)(qt*64 + row)*768 + h*64 + half;
#pragma unroll
        for (int i = 0; i < 8; i++) {
            float4 v = *(const float4*)(qp + i*4);
            v.x *= 0.125f; v.y *= 0.125f; v.z *= 0.125f; v.w *= 0.125f;
            *(float4*)&Qs[row*68 + half + i*4] = v;
        }
    }
    attn_issueKV(Kb0, Vb0, base, 0, h, tid);

    float o[8][4];
#pragma unroll
    for (int nt = 0; nt < 8; nt++)
#pragma unroll
        for (int i = 0; i < 4; i++) o[nt][i] = 0.f;
    float m0r = -1e30f, m1r = -1e30f, l0 = 0.f, l1 = 0.f;

    for (int kt = 0; kt < 49; kt++) {
        float* Ks = (kt & 1) ? Kb1 : Kb0;
        float* Vs = (kt & 1) ? Vb1 : Vb0;
        cp_wait0();
        __syncthreads();
        if (kt + 1 < 49)
            attn_issueKV((kt & 1) ? Kb0 : Kb1, (kt & 1) ? Vb0 : Vb1, base, kt+1, h, tid);

        float s[8][4];
#pragma unroll
        for (int nt = 0; nt < 8; nt++)
#pragma unroll
            for (int i = 0; i < 4; i++) s[nt][i] = 0.f;
#pragma unroll
        for (int kk = 0; kk < 8; kk++) {
            int kb = kk*8;
            u32 a[4];
            a[0] = su(&Qs[(qb+g)*68 + kb + t4]);
            a[1] = su(&Qs[(qb+g+8)*68 + kb + t4]);
            a[2] = su(&Qs[(qb+g)*68 + kb + t4 + 4]);
            a[3] = su(&Qs[(qb+g+8)*68 + kb + t4 + 4]);
#pragma unroll
            for (int nt = 0; nt < 8; nt++) {
                u32 bfr[2];
                bfr[0] = su(&Ks[(nt*8+g)*68 + kb + t4]);
                bfr[1] = su(&Ks[(nt*8+g)*68 + kb + t4 + 4]);
                mma_tf32(s[nt], a, bfr);
            }
        }

        float mx0 = -1e30f, mx1 = -1e30f;
#pragma unroll
        for (int nt = 0; nt < 8; nt++) {
            mx0 = fmaxf(mx0, fmaxf(s[nt][0], s[nt][1]));
            mx1 = fmaxf(mx1, fmaxf(s[nt][2], s[nt][3]));
        }
        mx0 = fmaxf(mx0, __shfl_xor_sync(0xffffffffu, mx0, 1));
        mx0 = fmaxf(mx0, __shfl_xor_sync(0xffffffffu, mx0, 2));
        mx1 = fmaxf(mx1, __shfl_xor_sync(0xffffffffu, mx1, 1));
        mx1 = fmaxf(mx1, __shfl_xor_sync(0xffffffffu, mx1, 2));
        float mn0 = fmaxf(m0r, mx0), mn1 = fmaxf(m1r, mx1);
        float sc0 = __expf(m0r - mn0), sc1 = __expf(m1r - mn1);
        m0r = mn0; m1r = mn1;
        l0 *= sc0; l1 *= sc1;
#pragma unroll
        for (int nt = 0; nt < 8; nt++) {
            o[nt][0] *= sc0; o[nt][1] *= sc0;
            o[nt][2] *= sc1; o[nt][3] *= sc1;
        }
        float rs0 = 0.f, rs1 = 0.f;
#pragma unroll
        for (int nt = 0; nt < 8; nt++) {
            float p0 = __expf(s[nt][0] - mn0);
            float p1 = __expf(s[nt][1] - mn0);
            float p2 = __expf(s[nt][2] - mn1);
            float p3 = __expf(s[nt][3] - mn1);
            rs0 += p0 + p1; rs1 += p2 + p3;
            *(float2*)&Ps[(qb+g)*68 + nt*8 + 2*t4]   = make_float2(f2tf(p0), f2tf(p1));
            *(float2*)&Ps[(qb+g+8)*68 + nt*8 + 2*t4] = make_float2(f2tf(p2), f2tf(p3));
        }
        rs0 += __shfl_xor_sync(0xffffffffu, rs0, 1);
        rs0 += __shfl_xor_sync(0xffffffffu, rs0, 2);
        rs1 += __shfl_xor_sync(0xffffffffu, rs1, 1);
        rs1 += __shfl_xor_sync(0xffffffffu, rs1, 2);
        l0 += rs0; l1 += rs1;
        __syncwarp();

#pragma unroll
        for (int kk = 0; kk < 8; kk++) {
            int kb = kk*8;
            u32 a[4];
            a[0] = su(&Ps[(qb+g)*68 + kb + t4]);
            a[1] = su(&Ps[(qb+g+8)*68 + kb + t4]);
            a[2] = su(&Ps[(qb+g)*68 + kb + t4 + 4]);
            a[3] = su(&Ps[(qb+g+8)*68 + kb + t4 + 4]);
#pragma unroll
            for (int nt = 0; nt < 8; nt++) {
                u32 bfr[2];
                bfr[0] = su(&Vs[(kb+t4)*72 + nt*8 + g]);
                bfr[1] = su(&Vs[(kb+t4+4)*72 + nt*8 + g]);
                mma_tf32(o[nt], a, bfr);
            }
        }
    }
    float inv0 = 1.f / l0, inv1 = 1.f / l1;
    int r0 = b*SEQ + qt*64 + qb + g;
#pragma unroll
    for (int nt = 0; nt < 8; nt++) {
        int col = h*64 + nt*8 + 2*t4;
        *(float2*)&out[(size_t)r0*256 + col]     = make_float2(f2tf(o[nt][0]*inv0), f2tf(o[nt][1]*inv0));
        *(float2*)&out[(size_t)(r0+8)*256 + col] = make_float2(f2tf(o[nt][2]*inv1), f2tf(o[nt][3]*inv1));
    }
}

// ---------------- sequence pooling softmax ----------------
__global__ void softpool_kernel() {
    __shared__ __align__(16) float e[SEQ];
    __shared__ __align__(16) float red[256];
    int b = blockIdx.x, tid = threadIdx.x;
    const float* lg = g_logits + b*SEQ;
    float mx = -1e30f;
    for (int n = tid; n < SEQ; n += 256) mx = fmaxf(mx, lg[n]);
    red[tid] = mx; __syncthreads();
    for (int s = 128; s; s >>= 1) { if (tid < s) red[tid] = fmaxf(red[tid], red[tid+s]); __syncthreads(); }
    mx = red[0]; __syncthreads();
    float sum = 0.f;
    for (int n = tid; n < SEQ; n += 256) { float ee = __expf(lg[n] - mx); e[n] = ee; sum += ee; }
    red[tid] = sum; __syncthreads();
    for (int s = 128; s; s >>= 1) { if (tid < s) red[tid] += red[tid+s]; __syncthreads(); }
    float inv = 1.f / red[0];
    const float* zb = g_hbuf + (size_t)b*SEQ*256;
    float acc = 0.f;
    for (int n = 0; n < SEQ; n++) acc = fmaf(e[n], zb[(size_t)n*256 + tid], acc);
    g_pooled[b*256 + tid] = acc * inv;
}

// ---------------- classifier head ----------------
__global__ void head_kernel(const float* __restrict__ hw, const float* __restrict__ hb,
                            float* __restrict__ out) {
    int t = threadIdx.x + blockIdx.x*blockDim.x;
    if (t >= NB*101) return;
    int b = t / 101, c = t % 101;
    const float* p = g_pooled + b*256;
    const float* w = hw + c*256;
    float acc = 0.f;
    for (int k = 0; k < 256; k++) acc = fmaf(p[k], w[k], acc);
    out[t] = acc + hb[c];
}

// ---------------- launcher ----------------
extern "C" void kernel_launch(void* const* d_in, const int* in_sizes, int n_in,
                              void* d_out, int out_size) {
    const float* x      = (const float*)d_in[0];
    const float* w1     = (const float*)d_in[1];
    const float* w2     = (const float*)d_in[2];
    const float* w3     = (const float*)d_in[3];
    const float* tokw   = (const float*)d_in[4];
    const float* pos    = (const float*)d_in[5];
    const float* ln1s   = (const float*)d_in[6];
    const float* ln1b   = (const float*)d_in[7];
    const float* qkvw   = (const float*)d_in[8];
    const float* qkvb   = (const float*)d_in[9];
    const float* projw  = (const float*)d_in[10];
    const float* projb  = (const float*)d_in[11];
    const float* ln2s   = (const float*)d_in[12];
    const float* ln2b   = (const float*)d_in[13];
    const float* fc1w   = (const float*)d_in[14];
    const float* fc1b   = (const float*)d_in[15];
    const float* fc2w   = (const float*)d_in[16];
    const float* fc2b   = (const float*)d_in[17];
    const float* lnfs   = (const float*)d_in[18];
    const float* lnfb   = (const float*)d_in[19];
    const float* poolw  = (const float*)d_in[20];
    const float* poolb  = (const float*)d_in[21];
    const float* headw  = (const float*)d_in[22];
    const float* headb  = (const float*)d_in[23];
    float* out = (float*)d_out;

    cudaFuncSetAttribute(attn_tc, cudaFuncAttributeMaxDynamicSharedMemorySize, ATTN_SMEM);

    float *zb, *hb_, *qk, *ob, *ml, *lg;
    float *wqkv, *wproj, *wfc1, *wfc2;
    cudaGetSymbolAddress((void**)&zb, g_z);
    cudaGetSymbolAddress((void**)&hb_, g_hbuf);
    cudaGetSymbolAddress((void**)&qk, g_qkv);
    cudaGetSymbolAddress((void**)&ob, g_obuf);
    cudaGetSymbolAddress((void**)&ml, g_mlp);
    cudaGetSymbolAddress((void**)&lg, g_logits);
    cudaGetSymbolAddress((void**)&wqkv, g_qkvwt);
    cudaGetSymbolAddress((void**)&wproj, g_projwt);
    cudaGetSymbolAddress((void**)&wfc1, g_fc1wt);
    cudaGetSymbolAddress((void**)&wfc2, g_fc2wt);

    pack_kernel<<<(9*3136 + 255)/256, 256>>>(w1, w2, w3);
    packw_kernel<<<(7*768*256 + 255)/256, 256>>>(qkvw, projw, fc1w, fc2w);
    conv1_tc<<<dim3(196, 36), 256>>>(x);
    conv2_kernel<<<dim3(196, 12), 256>>>();
    conv3_kernel<<<(NB*PLN + 255)/256, 256>>>();
    tok_kernel<<<dim3(49, 8, NB), 256>>>(tokw);
    pool_kernel<<<NB*256, 256>>>(pos);

    for (int lyr = 0; lyr < 7; lyr++) {
        ln_kernel<<<1568, 256>>>(zb, ln1s + lyr*256, ln1b + lyr*256, hb_, 1, 0, 0, 0);
        gemm_tc<<<dim3(12, 98), 128>>>(hb_, wqkv + (size_t)lyr*768*256, qkvb + lyr*768, 0, qk,
                                       MTOK, 768, 256, 0);
        attn_tc<<<dim3(49, 4, NB), 128, ATTN_SMEM>>>(qk, ob);
        gemm_tc<<<dim3(4, 98), 128>>>(ob, wproj + (size_t)lyr*256*256, projb + lyr*256, zb, zb,
                                      MTOK, 256, 256, 2);
        ln_kernel<<<1568, 256>>>(zb, ln2s + lyr*256, ln2b + lyr*256, hb_, 1, 0, 0, 0);
        gemm_tc<<<dim3(8, 98), 128>>>(hb_, wfc1 + (size_t)lyr*512*256, fc1b + lyr*512, 0, ml,
                                      MTOK, 512, 256, 1);
        gemm_tc<<<dim3(4, 98), 128>>>(ml, wfc2 + (size_t)lyr*256*512, fc2b + lyr*256, zb, zb,
                                      MTOK, 256, 512, 2);
    }

    ln_kernel<<<1568, 256>>>(zb, lnfs, lnfb, hb_, 0, poolw, poolb, lg);
    softpool_kernel<<<NB, 256>>>();
    head_kernel<<<2, 256>>>(headw, headb, out);
}